// round 12
// baseline (speedup 1.0000x reference)
#include <cuda_runtime.h>
#include <cstdint>
#include <cstddef>

// ============================================================================
// x [4,2048,4096] f32, w [4096,4096] int8-as-int32, out [8192,4096] f32.
// Baseline sm_103 ISA. GEMM via bf16 HMMA m16n8k16 (ints exact in bf16, f32
// accum). GEMM measured AT the legacy-HMMA hardware floor (~10.2 cyc/mma/SMSP;
// ncu tensor 70.6% == 7.2/10.2 exactly). R11: hide operand prep (quantize-A +
// pack-B) UNDER the GEMM via an in-kernel work-stealing chunk queue with per-kt
// completion counters. Launches: reset -> absmax -> gemm.
// Operand layouts (fragment-order blocked):
//   A block (16m x 16k) bf16 = 512 B: lane l -> {a0,a1,a2,a3} at blk*512 + l*16
//   B block ( 8n x 16k) bf16 = 256 B: lane l -> {b0,b1}       at blk*256 + l*8
// ============================================================================
#define K_DIM 4096
#define N_DIM 4096
#define M_DIM 8192

#define BM 128
#define BN 128
#define BK 64                   // four 16-k blocks per stage
#define STAGES 3
#define KITERS (K_DIM / BK)     // 64
#define KB16 (K_DIM / 16)       // 256 k-blocks globally

#define A_STAGE_BYTES (8 * 4 * 512)                   // 16384
#define B_STAGE_BYTES (16 * 4 * 256)                  // 16384
#define STAGE_BYTES (A_STAGE_BYTES + B_STAGE_BYTES)   // 32768
#define SMEM_TOTAL (STAGES * STAGE_BYTES)             // 98304

// Prep chunk queue: per kt, 64 A-panel chunks (128m x 64k) + 32 B-panel chunks
// (128n x 64k). kt-major ordering -> earliest-consumed tiles produced first.
#define CHUNKS_PER_KT 96
#define TOTAL_CHUNKS (KITERS * CHUNKS_PER_KT)          // 6144

// ============================================================================
// Device scratch
// ============================================================================
__device__ unsigned g_absmax;
__device__ unsigned g_prep_ctr;
__device__ unsigned g_ktdone[KITERS];
__device__ __align__(16) uint16_t g_xq[(size_t)M_DIM * K_DIM];  // 64 MiB bf16 blocked
__device__ __align__(16) uint16_t g_wq[(size_t)N_DIM * K_DIM];  // 32 MiB bf16 blocked

// ============================================================================
// PTX helpers
// ============================================================================
__device__ __forceinline__ uint32_t smem_u32(const void* p) {
    uint32_t a;
    asm("{ .reg .u64 t; cvta.to.shared.u64 t, %1; cvt.u32.u64 %0, t; }"
        : "=r"(a) : "l"(p));
    return a;
}

#define CP_ASYNC16(dst, src) \
    asm volatile("cp.async.cg.shared.global [%0], [%1], 16;" :: "r"(dst), "l"(src) : "memory")
#define CP_COMMIT() asm volatile("cp.async.commit_group;" ::: "memory")
#define CP_WAIT(n)  asm volatile("cp.async.wait_group %0;" :: "n"(n) : "memory")

#define LDS128(r0, r1, r2, r3, addr) \
    asm volatile("ld.shared.v4.b32 {%0,%1,%2,%3}, [%4];" \
        : "=r"(r0), "=r"(r1), "=r"(r2), "=r"(r3) : "r"(addr))
#define LDS64(r0, r1, addr) \
    asm volatile("ld.shared.v2.b32 {%0,%1}, [%2];" \
        : "=r"(r0), "=r"(r1) : "r"(addr))

// D(f32) = A(16x16 bf16) * B(16x8 bf16) + D
#define MMA_16816_BF16(d, a, b0, b1) \
    asm volatile( \
        "mma.sync.aligned.m16n8k16.row.col.f32.bf16.bf16.f32 " \
        "{%0,%1,%2,%3}, {%4,%5,%6,%7}, {%8,%9}, {%0,%1,%2,%3};" \
        : "+f"((d)[0]), "+f"((d)[1]), "+f"((d)[2]), "+f"((d)[3]) \
        : "r"((a)[0]), "r"((a)[1]), "r"((a)[2]), "r"((a)[3]), "r"(b0), "r"(b1))

__device__ __forceinline__ uint32_t bf16_bits(float f) {
    return __float_as_uint(f) >> 16;   // exact: small-int floats have 0 low mantissa
}
__device__ __forceinline__ uint32_t pack_bf16(float lo, float hi) {
    return bf16_bits(lo) | (bf16_bits(hi) << 16);
}

__device__ __forceinline__ unsigned ld_acquire_u32(const unsigned* p) {
    unsigned v;
    asm volatile("ld.acquire.gpu.u32 %0, [%1];" : "=r"(v) : "l"(p) : "memory");
    return v;
}

// ============================================================================
// Pass 0: reset queue state + absmax (per call: no caching across replays)
// ============================================================================
__global__ void reset_kernel() {
    int t = threadIdx.x;
    if (t < KITERS) g_ktdone[t] = 0u;
    if (t == KITERS) g_prep_ctr = 0u;
    if (t == KITERS + 1) g_absmax = 0u;
}

// ============================================================================
// Pass 1: absmax reduction over x
// ============================================================================
__global__ void absmax_kernel(const float4* __restrict__ x, int n4) {
    float m = 0.0f;
    int stride = gridDim.x * blockDim.x;
    for (int i = blockIdx.x * blockDim.x + threadIdx.x; i < n4; i += stride) {
        float4 v = x[i];
        m = fmaxf(m, fmaxf(fmaxf(fabsf(v.x), fabsf(v.y)),
                           fmaxf(fabsf(v.z), fabsf(v.w))));
    }
    #pragma unroll
    for (int o = 16; o > 0; o >>= 1)
        m = fmaxf(m, __shfl_xor_sync(0xFFFFFFFFu, m, o));
    __shared__ float wmax[8];
    if ((threadIdx.x & 31) == 0) wmax[threadIdx.x >> 5] = m;
    __syncthreads();
    if (threadIdx.x == 0) {
        float bm = wmax[0];
        #pragma unroll
        for (int i = 1; i < 8; i++) bm = fmaxf(bm, wmax[i]);
        atomicMax(&g_absmax, __float_as_uint(bm));   // vals >= 0: uint order ok
    }
}

// ============================================================================
// Prep chunks (run INSIDE the GEMM kernel by whichever CTA steals them).
// ============================================================================
__device__ __forceinline__ float q1(float v, float s) {
    return (float)__float2int_rz(fminf(fmaxf(v / s, -127.f), 127.f));
}

// A chunk: panel p (8 mb = 128 m-rows) x kt (4 kb = 64 k). 1024 lane-tasks.
__device__ void do_chunk_A(int panel, int ktc, const float* __restrict__ x,
                           float s, int tid) {
    #pragma unroll
    for (int rep = 0; rep < 2; rep++) {
        int i  = tid + rep * 512;
        int bi = i >> 5;                  // 0..31 block in chunk
        int l  = i & 31;
        int mb = panel * 8 + (bi >> 2);
        int kb = ktc * 4 + (bi & 3);
        int g = l >> 2, c = l & 3;
        int r0 = mb * 16 + g;
        int k0 = kb * 16 + 2 * c;
        const float* rlo = x + (size_t)r0 * K_DIM + k0;
        const float* rhi = x + (size_t)(r0 + 8) * K_DIM + k0;
        float2 v00 = *reinterpret_cast<const float2*>(rlo);       // a0
        float2 v10 = *reinterpret_cast<const float2*>(rhi);       // a1
        float2 v01 = *reinterpret_cast<const float2*>(rlo + 8);   // a2
        float2 v11 = *reinterpret_cast<const float2*>(rhi + 8);   // a3
        uint4 r;
        r.x = pack_bf16(q1(v00.x, s), q1(v00.y, s));
        r.y = pack_bf16(q1(v10.x, s), q1(v10.y, s));
        r.z = pack_bf16(q1(v01.x, s), q1(v01.y, s));
        r.w = pack_bf16(q1(v11.x, s), q1(v11.y, s));
        *reinterpret_cast<uint4*>(g_xq + ((size_t)mb * KB16 + kb) * 256 + l * 8) = r;
    }
}

// B chunk: panel p (16 nb = 128 n-rows) x kt (4 kb = 64 k). 2048 lane-tasks.
__device__ void do_chunk_B(int panel, int ktc, const int* __restrict__ w32, int tid) {
    #pragma unroll
    for (int rep = 0; rep < 4; rep++) {
        int i  = tid + rep * 512;
        int bi = i >> 5;                  // 0..63 block in chunk
        int l  = i & 31;
        int nb = panel * 16 + (bi >> 2);
        int kb = ktc * 4 + (bi & 3);
        int g = l >> 2, c = l & 3;
        int n  = nb * 8 + g;
        int k0 = kb * 16 + 2 * c;
        const int* row = w32 + (size_t)n * K_DIM + k0;
        int2 p0 = *reinterpret_cast<const int2*>(row);       // k0, k0+1
        int2 p1 = *reinterpret_cast<const int2*>(row + 8);   // k0+8, k0+9
        uint2 r;
        r.x = pack_bf16((float)p0.x, (float)p0.y);           // b0
        r.y = pack_bf16((float)p1.x, (float)p1.y);           // b1
        *reinterpret_cast<uint2*>(g_wq + ((size_t)nb * KB16 + kb) * 128 + l * 4) = r;
    }
}

// Block until all 96 chunks of tile t are done; steal queue work while waiting.
// Whole-CTA collective (uniform control flow via smem broadcast).
__device__ __noinline__ void ensure_tile(int t, const float* __restrict__ x,
                                         const int* __restrict__ w32, float s,
                                         int tid, unsigned* sflag) {
    while (true) {
        if (tid == 0) {
            unsigned cid = 0xFFFFFFFFu;
            if (ld_acquire_u32(&g_ktdone[t]) < CHUNKS_PER_KT)
                cid = atomicAdd(&g_prep_ctr, 1u);
            *sflag = cid;
        }
        __syncthreads();
        unsigned cid = *sflag;
        __syncthreads();
        if (cid == 0xFFFFFFFFu) return;            // tile ready
        if (cid < TOTAL_CHUNKS) {
            int ktc = cid / CHUNKS_PER_KT;
            int r   = cid % CHUNKS_PER_KT;
            if (r < 64) do_chunk_A(r, ktc, x, s, tid);
            else        do_chunk_B(r - 64, ktc, w32, tid);
            __threadfence();                       // publish stores gpu-wide
            __syncthreads();
            if (tid == 0) atomicAdd(&g_ktdone[ktc], 1u);
        } else {
            __nanosleep(200);                      // queue drained; chunk in flight
        }
    }
}

// ============================================================================
// Pass 2: bf16 GEMM with embedded work-stealing prep. CTA 128x128, 512 thr,
// 16 warps @ 32x32, BK=64, 3-stage cp.async pipeline (R9 mainloop verbatim).
// ============================================================================
__device__ __forceinline__ void load_stage(uint32_t sA, const uint16_t* gA,
                                           const uint16_t* gB, int kt, int tid) {
    uint32_t sB = sA + A_STAGE_BYTES;
    #pragma unroll
    for (int i = 0; i < 2; i++) {
        int idx = tid + i * 512;
        int blk = idx >> 5;
        int mb = blk >> 2, kb = blk & 3;
        const uint16_t* src = gA + (size_t)mb * (KB16 * 256)
                                 + (size_t)(kt * 4 + kb) * 256 + (idx & 31) * 8;
        CP_ASYNC16(sA + idx * 16, src);
    }
    #pragma unroll
    for (int i = 0; i < 2; i++) {
        int idx = tid + i * 512;
        int blk = idx >> 4;
        int nb = blk >> 2, kb = blk & 3;
        const uint16_t* src = gB + (size_t)nb * (KB16 * 128)
                                 + (size_t)(kt * 4 + kb) * 128 + (idx & 15) * 8;
        CP_ASYNC16(sB + idx * 16, src);
    }
}

__global__ __launch_bounds__(512) void gemm_bf16_kernel(
    float* __restrict__ out,
    const float* __restrict__ wscale,
    const float* __restrict__ bias,
    const float* __restrict__ x,
    const int* __restrict__ w32)
{
    extern __shared__ char smem[];
    __shared__ unsigned sflag;
    uint32_t sbase = smem_u32(smem);
    int tid  = threadIdx.x;
    int wid  = tid >> 5;
    int lane = tid & 31;
    int m0 = blockIdx.x * BM;
    int n0 = blockIdx.y * BN;

    int warp_m = (wid & 3) * 32;
    int warp_n = (wid >> 2) * 32;

    const uint16_t* gA = g_xq + (size_t)m0 * K_DIM;
    const uint16_t* gB = g_wq + (size_t)n0 * K_DIM;

    int g = lane >> 2;
    int c = lane & 3;

    uint32_t a_base = (uint32_t)((warp_m >> 4) * 4) * 512 + (uint32_t)lane * 16;
    uint32_t b_base = A_STAGE_BYTES + (uint32_t)((warp_n >> 3) * 4) * 256 + (uint32_t)lane * 8;

    float s = __uint_as_float(g_absmax) / 127.0f;   // set by absmax_kernel

    float acc[2][4][4];
    #pragma unroll
    for (int mi = 0; mi < 2; mi++)
        #pragma unroll
        for (int ni = 0; ni < 4; ni++)
            #pragma unroll
            for (int k = 0; k < 4; k++) acc[mi][ni][k] = 0.0f;

    #pragma unroll
    for (int t = 0; t < STAGES - 1; t++) {
        ensure_tile(t, x, w32, s, tid, &sflag);
        load_stage(sbase + t * STAGE_BYTES, gA, gB, t, tid);
        CP_COMMIT();
    }

    for (int kt = 0; kt < KITERS; kt++) {
        CP_WAIT(STAGES - 2);
        __syncthreads();

        int t = kt + STAGES - 1;
        if (t < KITERS) {
            ensure_tile(t, x, w32, s, tid, &sflag);
            load_stage(sbase + ((kt + STAGES - 1) % STAGES) * STAGE_BYTES, gA, gB, t, tid);
        }
        CP_COMMIT();

        uint32_t sA = sbase + (kt % STAGES) * STAGE_BYTES;

        #pragma unroll
        for (int ks = 0; ks < 4; ks++) {
            uint32_t afr[2][4];
            #pragma unroll
            for (int mi = 0; mi < 2; mi++)
                LDS128(afr[mi][0], afr[mi][1], afr[mi][2], afr[mi][3],
                       sA + a_base + (uint32_t)((mi * 4 + ks) * 512));
            uint32_t bfr[4][2];
            #pragma unroll
            for (int ni = 0; ni < 4; ni++)
                LDS64(bfr[ni][0], bfr[ni][1],
                      sA + b_base + (uint32_t)((ni * 4 + ks) * 256));
            #pragma unroll
            for (int mi = 0; mi < 2; mi++)
                #pragma unroll
                for (int ni = 0; ni < 4; ni++)
                    MMA_16816_BF16(acc[mi][ni], afr[mi], bfr[ni][0], bfr[ni][1]);
        }
    }

    // Epilogue: scale + bias, f32x2 stores
    float combined = s * wscale[0];
    #pragma unroll
    for (int mi = 0; mi < 2; mi++) {
        #pragma unroll
        for (int ni = 0; ni < 4; ni++) {
            int row = m0 + warp_m + mi * 16 + g;
            int col = n0 + warp_n + ni * 8 + c * 2;
            float2 bv = *reinterpret_cast<const float2*>(bias + col);
            float2 v0, v1;
            v0.x = acc[mi][ni][0] * combined + bv.x;
            v0.y = acc[mi][ni][1] * combined + bv.y;
            v1.x = acc[mi][ni][2] * combined + bv.x;
            v1.y = acc[mi][ni][3] * combined + bv.y;
            *reinterpret_cast<float2*>(out + (size_t)row * N_DIM + col) = v0;
            *reinterpret_cast<float2*>(out + (size_t)(row + 8) * N_DIM + col) = v1;
        }
    }
}

// ============================================================================
// kernel_launch: reset -> absmax -> gemm (prep rides inside the GEMM)
// ============================================================================
extern "C" void kernel_launch(void* const* d_in, const int* in_sizes, int n_in,
                              void* d_out, int out_size) {
    const float* x   = (const float*)d_in[0];
    const int*   w32 = (const int*)d_in[1];
    const float* ws  = (const float*)d_in[2];
    const float* b   = (const float*)d_in[3];
    float* out = (float*)d_out;

    int n4 = in_sizes[0] / 4;

    cudaFuncSetAttribute(gemm_bf16_kernel,
                         cudaFuncAttributeMaxDynamicSharedMemorySize, SMEM_TOTAL);

    reset_kernel<<<1, 128>>>();
    absmax_kernel<<<1024, 256>>>((const float4*)x, n4);

    dim3 grid(M_DIM / BM, N_DIM / BN);   // 64 x 32
    gemm_bf16_kernel<<<grid, 512, SMEM_TOTAL>>>(out, ws, b, x, w32);
}

// round 13
// speedup vs baseline: 2.1959x; 2.1959x over previous
#include <cuda_runtime.h>
#include <cstdint>
#include <cstddef>

// ============================================================================
// x [4,2048,4096] f32, w [4096,4096] int8-as-int32, out [8192,4096] f32.
// Baseline sm_103 ISA. GEMM via bf16 HMMA m16n8k16 (ints exact in bf16, f32
// accum) — measured at the legacy-HMMA hardware floor (~10.2 cyc/mma/SMSP),
// reproduced at 641-644 us across three structures. R13 = best-known R11
// structure with the reset launch removed: absmax uses plain-stored partials
// (no init, no atomics); xprep reduces them in-block; xprep block 0 publishes
// g_absmax for the GEMM epilogue (single writer).
// Operand layouts (fragment-order blocked):
//   A block (16m x 16k) bf16 = 512 B: lane l -> {a0,a1,a2,a3} at blk*512 + l*16
//   B block ( 8n x 16k) bf16 = 256 B: lane l -> {b0,b1}       at blk*256 + l*8
// Launches: [absmax-partial || wprep] -> xprep -> gemm.
// ============================================================================
#define K_DIM 4096
#define N_DIM 4096
#define M_DIM 8192

#define BM 128
#define BN 128
#define BK 64                   // four 16-k blocks per stage
#define STAGES 3
#define KITERS (K_DIM / BK)     // 64
#define KB16 (K_DIM / 16)       // 256 k-blocks globally

#define A_STAGE_BYTES (8 * 4 * 512)                   // 16384
#define B_STAGE_BYTES (16 * 4 * 256)                  // 16384
#define STAGE_BYTES (A_STAGE_BYTES + B_STAGE_BYTES)   // 32768
#define SMEM_TOTAL (STAGES * STAGE_BYTES)             // 98304

#define ABSMAX_BLOCKS 1024
#define W_PREP_BLOCKS ((N_DIM / 8) * KB16 * 32 / 256)    // 16384
#define X_PREP_BLOCKS ((M_DIM / 16) * KB16 * 32 / 256)   // 16384

// ============================================================================
// Device scratch
// ============================================================================
__device__ unsigned g_absmax;                              // written by xprep blk 0
__device__ __align__(16) float g_partial[ABSMAX_BLOCKS];   // plain-stored partials
__device__ __align__(16) uint16_t g_xq[(size_t)M_DIM * K_DIM];  // 64 MiB bf16 blocked
__device__ __align__(16) uint16_t g_wq[(size_t)N_DIM * K_DIM];  // 32 MiB bf16 blocked

// ============================================================================
// PTX helpers
// ============================================================================
__device__ __forceinline__ uint32_t smem_u32(const void* p) {
    uint32_t a;
    asm("{ .reg .u64 t; cvta.to.shared.u64 t, %1; cvt.u32.u64 %0, t; }"
        : "=r"(a) : "l"(p));
    return a;
}

#define CP_ASYNC16(dst, src) \
    asm volatile("cp.async.cg.shared.global [%0], [%1], 16;" :: "r"(dst), "l"(src) : "memory")
#define CP_COMMIT() asm volatile("cp.async.commit_group;" ::: "memory")
#define CP_WAIT(n)  asm volatile("cp.async.wait_group %0;" :: "n"(n) : "memory")

#define LDS128(r0, r1, r2, r3, addr) \
    asm volatile("ld.shared.v4.b32 {%0,%1,%2,%3}, [%4];" \
        : "=r"(r0), "=r"(r1), "=r"(r2), "=r"(r3) : "r"(addr))
#define LDS64(r0, r1, addr) \
    asm volatile("ld.shared.v2.b32 {%0,%1}, [%2];" \
        : "=r"(r0), "=r"(r1) : "r"(addr))

// D(f32) = A(16x16 bf16) * B(16x8 bf16) + D
#define MMA_16816_BF16(d, a, b0, b1) \
    asm volatile( \
        "mma.sync.aligned.m16n8k16.row.col.f32.bf16.bf16.f32 " \
        "{%0,%1,%2,%3}, {%4,%5,%6,%7}, {%8,%9}, {%0,%1,%2,%3};" \
        : "+f"((d)[0]), "+f"((d)[1]), "+f"((d)[2]), "+f"((d)[3]) \
        : "r"((a)[0]), "r"((a)[1]), "r"((a)[2]), "r"((a)[3]), "r"(b0), "r"(b1))

__device__ __forceinline__ uint32_t bf16_bits(float f) {
    return __float_as_uint(f) >> 16;   // exact: small-int floats have 0 low mantissa
}
__device__ __forceinline__ uint32_t pack_bf16(float lo, float hi) {
    return bf16_bits(lo) | (bf16_bits(hi) << 16);
}

// ============================================================================
// Pass 1 (fused): absmax partials (blocks [0,1024)) + weight pack (rest).
// Partials are plain stores -> no reset kernel needed.
// ============================================================================
__global__ void absmax_wprep_kernel(const float4* __restrict__ x, int n4,
                                    const int* __restrict__ w32) {
    if (blockIdx.x < ABSMAX_BLOCKS) {
        float m = 0.0f;
        int stride = ABSMAX_BLOCKS * blockDim.x;
        for (int i = blockIdx.x * blockDim.x + threadIdx.x; i < n4; i += stride) {
            float4 v = x[i];
            m = fmaxf(m, fmaxf(fmaxf(fabsf(v.x), fabsf(v.y)),
                               fmaxf(fabsf(v.z), fabsf(v.w))));
        }
        #pragma unroll
        for (int o = 16; o > 0; o >>= 1)
            m = fmaxf(m, __shfl_xor_sync(0xFFFFFFFFu, m, o));
        __shared__ float wmax[8];
        if ((threadIdx.x & 31) == 0) wmax[threadIdx.x >> 5] = m;
        __syncthreads();
        if (threadIdx.x == 0) {
            float bm = wmax[0];
            #pragma unroll
            for (int i = 1; i < 8; i++) bm = fmaxf(bm, wmax[i]);
            g_partial[blockIdx.x] = bm;            // plain store, no init needed
        }
    } else {
        int id  = (blockIdx.x - ABSMAX_BLOCKS) * 256 + threadIdx.x;
        int l   = id & 31;
        int blk = id >> 5;                   // 0 .. 131071
        int kb  = blk & (KB16 - 1);
        int nb  = blk >> 8;
        int g   = l >> 2;
        int c   = l & 3;
        int n   = nb * 8 + g;
        int k0  = kb * 16 + 2 * c;
        const int* row = w32 + (size_t)n * K_DIM + k0;
        int2 p0 = *reinterpret_cast<const int2*>(row);       // k0, k0+1
        int2 p1 = *reinterpret_cast<const int2*>(row + 8);   // k0+8, k0+9
        uint2 r;
        r.x = pack_bf16((float)p0.x, (float)p0.y);           // b0
        r.y = pack_bf16((float)p1.x, (float)p1.y);           // b1
        *reinterpret_cast<uint2*>(g_wq + (size_t)blk * 128 + l * 4) = r;
    }
}

// ============================================================================
// Pass 2: quantize x -> g_xq (bf16, A-fragment blocked layout).
// Each block first reduces the 1024 partials (4 KB, L2-hot, overlaps with the
// independent x loads). Block 0 also publishes g_absmax for the GEMM.
// ============================================================================
__device__ __forceinline__ float q1(float v, float s) {
    return (float)__float2int_rz(fminf(fmaxf(v / s, -127.f), 127.f));
}

__global__ void xprep_kernel(const float* __restrict__ x) {
    __shared__ float wmax[8];
    __shared__ float sbm;

    int tid = threadIdx.x;
    int id  = blockIdx.x * 256 + tid;
    int l   = id & 31;
    int blk = id >> 5;                   // 0 .. 131071
    int kb  = blk & (KB16 - 1);
    int mb  = blk >> 8;                  // 0 .. 511
    int g   = l >> 2;
    int c   = l & 3;
    int r0  = mb * 16 + g;
    int k0  = kb * 16 + 2 * c;

    // Independent x loads (issue before the partial reduction to overlap)
    const float* rlo = x + (size_t)r0 * K_DIM + k0;
    const float* rhi = x + (size_t)(r0 + 8) * K_DIM + k0;
    float2 v00 = *reinterpret_cast<const float2*>(rlo);       // a0
    float2 v10 = *reinterpret_cast<const float2*>(rhi);       // a1
    float2 v01 = *reinterpret_cast<const float2*>(rlo + 8);   // a2
    float2 v11 = *reinterpret_cast<const float2*>(rhi + 8);   // a3

    // In-block reduction of 1024 partials: 4 per thread
    float4 p = reinterpret_cast<const float4*>(g_partial)[tid];
    float m = fmaxf(fmaxf(p.x, p.y), fmaxf(p.z, p.w));
    #pragma unroll
    for (int o = 16; o > 0; o >>= 1)
        m = fmaxf(m, __shfl_xor_sync(0xFFFFFFFFu, m, o));
    if ((tid & 31) == 0) wmax[tid >> 5] = m;
    __syncthreads();
    if (tid == 0) {
        float bm = wmax[0];
        #pragma unroll
        for (int i = 1; i < 8; i++) bm = fmaxf(bm, wmax[i]);
        sbm = bm;
        if (blockIdx.x == 0) g_absmax = __float_as_uint(bm);  // single writer
    }
    __syncthreads();
    float s = sbm / 127.0f;

    uint4 r;
    r.x = pack_bf16(q1(v00.x, s), q1(v00.y, s));
    r.y = pack_bf16(q1(v10.x, s), q1(v10.y, s));
    r.z = pack_bf16(q1(v01.x, s), q1(v01.y, s));
    r.w = pack_bf16(q1(v11.x, s), q1(v11.y, s));
    *reinterpret_cast<uint4*>(g_xq + (size_t)blk * 256 + l * 8) = r;
}

// ============================================================================
// Pass 3: bf16 GEMM (R9/R11 verbatim — measured best, 641-644 us).
// CTA 128x128, 512 threads, 16 warps @ 32x32, BK=64, 3-stage cp.async.
// ============================================================================
__device__ __forceinline__ void load_stage(uint32_t sA, const uint16_t* gA,
                                           const uint16_t* gB, int kt, int tid) {
    uint32_t sB = sA + A_STAGE_BYTES;
    #pragma unroll
    for (int i = 0; i < 2; i++) {
        int idx = tid + i * 512;
        int blk = idx >> 5;
        int mb = blk >> 2, kb = blk & 3;
        const uint16_t* src = gA + (size_t)mb * (KB16 * 256)
                                 + (size_t)(kt * 4 + kb) * 256 + (idx & 31) * 8;
        CP_ASYNC16(sA + idx * 16, src);
    }
    #pragma unroll
    for (int i = 0; i < 2; i++) {
        int idx = tid + i * 512;
        int blk = idx >> 4;
        int nb = blk >> 2, kb = blk & 3;
        const uint16_t* src = gB + (size_t)nb * (KB16 * 128)
                                 + (size_t)(kt * 4 + kb) * 128 + (idx & 15) * 8;
        CP_ASYNC16(sB + idx * 16, src);
    }
}

__global__ __launch_bounds__(512, 2) void gemm_bf16_kernel(
    float* __restrict__ out,
    const float* __restrict__ wscale,
    const float* __restrict__ bias)
{
    extern __shared__ char smem[];
    uint32_t sbase = smem_u32(smem);
    int tid  = threadIdx.x;
    int wid  = tid >> 5;
    int lane = tid & 31;
    int m0 = blockIdx.x * BM;
    int n0 = blockIdx.y * BN;

    int warp_m = (wid & 3) * 32;
    int warp_n = (wid >> 2) * 32;

    const uint16_t* gA = g_xq + (size_t)m0 * K_DIM;
    const uint16_t* gB = g_wq + (size_t)n0 * K_DIM;

    int g = lane >> 2;
    int c = lane & 3;

    uint32_t a_base = (uint32_t)((warp_m >> 4) * 4) * 512 + (uint32_t)lane * 16;
    uint32_t b_base = A_STAGE_BYTES + (uint32_t)((warp_n >> 3) * 4) * 256 + (uint32_t)lane * 8;

    float acc[2][4][4];
    #pragma unroll
    for (int mi = 0; mi < 2; mi++)
        #pragma unroll
        for (int ni = 0; ni < 4; ni++)
            #pragma unroll
            for (int k = 0; k < 4; k++) acc[mi][ni][k] = 0.0f;

    #pragma unroll
    for (int t = 0; t < STAGES - 1; t++) {
        load_stage(sbase + t * STAGE_BYTES, gA, gB, t, tid);
        CP_COMMIT();
    }

    for (int kt = 0; kt < KITERS; kt++) {
        CP_WAIT(STAGES - 2);
        __syncthreads();

        int t = kt + STAGES - 1;
        if (t < KITERS)
            load_stage(sbase + ((kt + STAGES - 1) % STAGES) * STAGE_BYTES, gA, gB, t, tid);
        CP_COMMIT();

        uint32_t sA = sbase + (kt % STAGES) * STAGE_BYTES;

        #pragma unroll
        for (int ks = 0; ks < 4; ks++) {
            uint32_t afr[2][4];
            #pragma unroll
            for (int mi = 0; mi < 2; mi++)
                LDS128(afr[mi][0], afr[mi][1], afr[mi][2], afr[mi][3],
                       sA + a_base + (uint32_t)((mi * 4 + ks) * 512));
            uint32_t bfr[4][2];
            #pragma unroll
            for (int ni = 0; ni < 4; ni++)
                LDS64(bfr[ni][0], bfr[ni][1],
                      sA + b_base + (uint32_t)((ni * 4 + ks) * 256));
            #pragma unroll
            for (int mi = 0; mi < 2; mi++)
                #pragma unroll
                for (int ni = 0; ni < 4; ni++)
                    MMA_16816_BF16(acc[mi][ni], afr[mi], bfr[ni][0], bfr[ni][1]);
        }
    }

    // Epilogue: scale + bias, f32x2 stores
    float combined = (__uint_as_float(g_absmax) / 127.0f) * wscale[0];
    #pragma unroll
    for (int mi = 0; mi < 2; mi++) {
        #pragma unroll
        for (int ni = 0; ni < 4; ni++) {
            int row = m0 + warp_m + mi * 16 + g;
            int col = n0 + warp_n + ni * 8 + c * 2;
            float2 bv = *reinterpret_cast<const float2*>(bias + col);
            float2 v0, v1;
            v0.x = acc[mi][ni][0] * combined + bv.x;
            v0.y = acc[mi][ni][1] * combined + bv.y;
            v1.x = acc[mi][ni][2] * combined + bv.x;
            v1.y = acc[mi][ni][3] * combined + bv.y;
            *reinterpret_cast<float2*>(out + (size_t)row * N_DIM + col) = v0;
            *reinterpret_cast<float2*>(out + (size_t)(row + 8) * N_DIM + col) = v1;
        }
    }
}

// ============================================================================
// kernel_launch: [absmax-partial || wprep] -> xprep -> gemm   (3 launches)
// ============================================================================
extern "C" void kernel_launch(void* const* d_in, const int* in_sizes, int n_in,
                              void* d_out, int out_size) {
    const float* x   = (const float*)d_in[0];
    const int*   w32 = (const int*)d_in[1];
    const float* ws  = (const float*)d_in[2];
    const float* b   = (const float*)d_in[3];
    float* out = (float*)d_out;

    int n4 = in_sizes[0] / 4;

    cudaFuncSetAttribute(gemm_bf16_kernel,
                         cudaFuncAttributeMaxDynamicSharedMemorySize, SMEM_TOTAL);

    absmax_wprep_kernel<<<ABSMAX_BLOCKS + W_PREP_BLOCKS, 256>>>((const float4*)x, n4, w32);
    xprep_kernel<<<X_PREP_BLOCKS, 256>>>(x);

    dim3 grid(M_DIM / BM, N_DIM / BN);   // 64 x 32
    gemm_bf16_kernel<<<grid, 512, SMEM_TOTAL>>>(out, ws, b);
}